// round 5
// baseline (speedup 1.0000x reference)
#include <cuda_runtime.h>
#include <cuda_bf16.h>
#include <math.h>

#define N_NODES_MAX 100000
#define D_IN        256
#define H1          16
#define H2          32
#define KT          32     // k-tile for gemm1
#define G_THREADS   128    // threads per gemm1 block
#define G_ROWS      256    // rows per gemm1 block (2 per thread)

#define FMA2(d, a, b) \
    asm("fma.rn.f32x2 %0, %1, %2, %0;" : "+l"(d) : "l"(a), "l"(b))

// Scratch (device globals — BSS zero-init; every call leaves them zeroed again,
// so the kernel is deterministic across graph replays).
__device__ __align__(256) float g_y[N_NODES_MAX * H1];   // x @ W1
__device__ __align__(256) float g_a[N_NODES_MAX * H1];   // spmm accumulator (pre-relu)
__device__ __align__(256) float g_s[N_NODES_MAX];        // s[j] = sum_{e: col==j} val[e]
__device__ __align__(256) float g_t[H1];                 // t = sum_i s[i]*relu(a[i])
__device__ unsigned g_ticket;                            // last-block ticket

// ---------------------------------------------------------------------------
// y = x @ W1   (N x 256) @ (256 x 16)
// Coalesced LDG into a transposed pad-257 shared tile (conflict-free both
// ways); 2 rows per thread (W reads amortized); packed fma.rn.f32x2 math.
// ---------------------------------------------------------------------------
__global__ void gemm1_kernel(const float* __restrict__ x,
                             const float* __restrict__ W1, int n) {
    extern __shared__ float smem[];
    float* sW = smem;                    // [D_IN*H1] = 4096 floats (16 KB)
    float* sx = smem + D_IN * H1;        // [KT][257] transposed x tile

    int tid = threadIdx.x;
    for (int i = tid; i < D_IN * H1 / 4; i += G_THREADS)
        reinterpret_cast<float4*>(sW)[i] = reinterpret_cast<const float4*>(W1)[i];

    int row0 = blockIdx.x * G_ROWS;
    int rA = row0 + tid;
    int rB = row0 + tid + G_THREADS;

    unsigned long long accA[8], accB[8];   // f32x2 pairs: features (0,1)..(14,15)
#pragma unroll
    for (int j = 0; j < 8; j++) { accA[j] = 0ull; accB[j] = 0ull; }

    for (int kt = 0; kt < D_IN; kt += KT) {
        __syncthreads();   // protect sx (prev-iter reads / W1 load on iter 0)
        // Stage tile: 256 rows x 32 floats = 2048 float4; 16 per thread.
        // lanes 0..7 cover one row's 8 float4 -> LDG fully coalesced.
#pragma unroll
        for (int i = 0; i < 16; i++) {
            int idx = tid + i * G_THREADS;
            int r = idx >> 3, kv = idx & 7;
            if (row0 + r < n) {
                float4 v = __ldg(reinterpret_cast<const float4*>(
                    x + (size_t)(row0 + r) * D_IN + kt + kv * 4));
                int k = kv * 4;
                sx[(k + 0) * 257 + r] = v.x;   // bank (k+r)%32: conflict-free
                sx[(k + 1) * 257 + r] = v.y;
                sx[(k + 2) * 257 + r] = v.z;
                sx[(k + 3) * 257 + r] = v.w;
            }
        }
        __syncthreads();
#pragma unroll
        for (int kk = 0; kk < KT; kk++) {
            float xa = sx[kk * 257 + tid];
            float xb = sx[kk * 257 + tid + G_THREADS];
            unsigned long long xa2, xb2;
            asm("mov.b64 %0, {%1, %1};" : "=l"(xa2) : "f"(xa));
            asm("mov.b64 %0, {%1, %1};" : "=l"(xb2) : "f"(xb));
            const ulonglong2* wp =
                reinterpret_cast<const ulonglong2*>(sW + (kt + kk) * H1);
            ulonglong2 w01 = wp[0], w23 = wp[1], w45 = wp[2], w67 = wp[3];
            FMA2(accA[0], xa2, w01.x); FMA2(accA[1], xa2, w01.y);
            FMA2(accA[2], xa2, w23.x); FMA2(accA[3], xa2, w23.y);
            FMA2(accA[4], xa2, w45.x); FMA2(accA[5], xa2, w45.y);
            FMA2(accA[6], xa2, w67.x); FMA2(accA[7], xa2, w67.y);
            FMA2(accB[0], xb2, w01.x); FMA2(accB[1], xb2, w01.y);
            FMA2(accB[2], xb2, w23.x); FMA2(accB[3], xb2, w23.y);
            FMA2(accB[4], xb2, w45.x); FMA2(accB[5], xb2, w45.y);
            FMA2(accB[6], xb2, w67.x); FMA2(accB[7], xb2, w67.y);
        }
    }
    if (rA < n) {
        ulonglong2* yr = reinterpret_cast<ulonglong2*>(g_y + (size_t)rA * H1);
        yr[0] = make_ulonglong2(accA[0], accA[1]);
        yr[1] = make_ulonglong2(accA[2], accA[3]);
        yr[2] = make_ulonglong2(accA[4], accA[5]);
        yr[3] = make_ulonglong2(accA[6], accA[7]);
    }
    if (rB < n) {
        ulonglong2* yr = reinterpret_cast<ulonglong2*>(g_y + (size_t)rB * H1);
        yr[0] = make_ulonglong2(accB[0], accB[1]);
        yr[1] = make_ulonglong2(accB[2], accB[3]);
        yr[2] = make_ulonglong2(accB[4], accB[5]);
        yr[3] = make_ulonglong2(accB[6], accB[7]);
    }
}

// ---------------------------------------------------------------------------
// Edge pass: a[r] += v * y[c] via red.global.add.v4.f32 (4 lanes per edge)
//            s[c] += v (lane 0 of each quad)
// ---------------------------------------------------------------------------
__global__ void edge_kernel(const int* __restrict__ rows,
                            const int* __restrict__ cols,
                            const float* __restrict__ vals, int e_count) {
    int gid = blockIdx.x * blockDim.x + threadIdx.x;
    int q = gid & 3;           // quarter of the 16-wide feature row
    int e = gid >> 2;
    if (e >= e_count) return;

    int r = __ldg(rows + e);
    int c = __ldg(cols + e);
    float v = __ldg(vals + e);

    const float4 yv = __ldg(reinterpret_cast<const float4*>(g_y + (size_t)c * H1 + q * 4));
    float px = v * yv.x, py = v * yv.y, pz = v * yv.z, pw = v * yv.w;
    float* dst = g_a + (size_t)r * H1 + q * 4;
    asm volatile("red.global.add.v4.f32 [%0], {%1, %2, %3, %4};"
                 :: "l"(dst), "f"(px), "f"(py), "f"(pz), "f"(pw) : "memory");
    if (q == 0) atomicAdd(&g_s[c], v);
}

// ---------------------------------------------------------------------------
// t[f] = sum_i s[i] * relu(a[i][f]); self-cleans g_a/g_s; last block computes
// the final output and cleans g_t/g_ticket.
// ---------------------------------------------------------------------------
__global__ void reduce_final_kernel(int n,
                                    const float* __restrict__ W2,
                                    const float* __restrict__ w_out,
                                    const float* __restrict__ b_out,
                                    float* __restrict__ out) {
    __shared__ float4 red[256];
    __shared__ bool is_last;
    int tid = threadIdx.x;
    int g = tid & 3;  // feature group: covers features [4g, 4g+4)
    const float4 z4 = {0.f, 0.f, 0.f, 0.f};
    float4 acc = z4;
    int total = n * 4;
    int stride = gridDim.x * blockDim.x;
    for (int idx = blockIdx.x * blockDim.x + tid; idx < total; idx += stride) {
        int i = idx >> 2;
        float4* ap = reinterpret_cast<float4*>(g_a + (size_t)i * H1 + g * 4);
        float4 av = *ap;
        float s = 0.0f;
        if (g == 0) { s = g_s[i]; g_s[i] = 0.0f; }   // sole reader of g_s[i]
        s = __shfl_sync(0xffffffffu, s, (tid & 31) & ~3);
        *ap = z4;                                     // self-clean g_a
        acc.x += s * fmaxf(av.x, 0.f);
        acc.y += s * fmaxf(av.y, 0.f);
        acc.z += s * fmaxf(av.z, 0.f);
        acc.w += s * fmaxf(av.w, 0.f);
    }
    red[tid] = acc;
    __syncthreads();
#pragma unroll
    for (int off = 128; off >= 4; off >>= 1) {
        if (tid < off) {
            float4 o = red[tid + off];
            red[tid].x += o.x; red[tid].y += o.y; red[tid].z += o.z; red[tid].w += o.w;
        }
        __syncthreads();
    }
    if (tid < 4) {
        float4 r4 = red[tid];
        float* dst = g_t + tid * 4;
        asm volatile("red.global.add.v4.f32 [%0], {%1, %2, %3, %4};"
                     :: "l"(dst), "f"(r4.x), "f"(r4.y), "f"(r4.z), "f"(r4.w) : "memory");
    }
    __threadfence();
    if (tid == 0) {
        unsigned done = atomicAdd(&g_ticket, 1u);
        is_last = (done == gridDim.x - 1);
    }
    __syncthreads();
    if (is_last) {
        __threadfence();  // pair with producers' fences
        float z = 0.0f;
        if (tid < H2) {
#pragma unroll
            for (int fi = 0; fi < H1; fi++) z += g_t[fi] * W2[fi * H2 + tid];
        }
        __syncthreads();
        if (tid < H1) g_t[tid] = 0.0f;   // self-clean g_t
        if (tid == 0) g_ticket = 0u;     // self-clean ticket
        if (tid < H2) {
            float p = z * w_out[tid];
#pragma unroll
            for (int o = 16; o > 0; o >>= 1) p += __shfl_xor_sync(0xffffffffu, p, o);
            if (tid == 0) out[0] = 1.0f / (1.0f + expf(-(p + b_out[0])));
        }
    }
}

// ---------------------------------------------------------------------------
extern "C" void kernel_launch(void* const* d_in, const int* in_sizes, int n_in,
                              void* d_out, int out_size) {
    const float* x     = (const float*)d_in[0];
    const float* vals  = (const float*)d_in[1];
    const float* W1    = (const float*)d_in[2];
    const float* W2    = (const float*)d_in[3];
    const float* w_out = (const float*)d_in[4];
    const float* b_out = (const float*)d_in[5];
    const int*   rows  = (const int*)d_in[6];
    const int*   cols  = (const int*)d_in[7];

    int n = in_sizes[0] / D_IN;   // 100000
    int e = in_sizes[1];          // 3200000

    int smem_bytes = (D_IN * H1 + KT * 257) * sizeof(float);  // 49280 B
    cudaFuncSetAttribute(gemm1_kernel,
                         cudaFuncAttributeMaxDynamicSharedMemorySize, smem_bytes);

    gemm1_kernel<<<(n + G_ROWS - 1) / G_ROWS, G_THREADS, smem_bytes>>>(x, W1, n);
    {
        long long work = (long long)e * 4;
        int blocks = (int)((work + 255) / 256);
        edge_kernel<<<blocks, 256>>>(rows, cols, vals, e);
    }
    reduce_final_kernel<<<1024, 256>>>(n, W2, w_out, b_out, (float*)d_out);
}

// round 6
// speedup vs baseline: 1.3077x; 1.3077x over previous
#include <cuda_runtime.h>
#include <cuda_bf16.h>
#include <math.h>

#define N_NODES_MAX 100000
#define D_IN        256
#define H1          16
#define H2          32
#define KT          32     // k-tile for gemm1
#define G_THREADS   256    // threads per gemm1 block (1 row per thread)

#define FMA2(d, a, b) \
    asm("fma.rn.f32x2 %0, %1, %2, %0;" : "+l"(d) : "l"(a), "l"(b))

// Scratch (device globals — BSS zero-init; every call leaves them zeroed again,
// so the kernel is deterministic across graph replays).
__device__ __align__(256) float g_y[N_NODES_MAX * H1];   // x @ W1
__device__ __align__(256) float g_a[N_NODES_MAX * H1];   // spmm accumulator (pre-relu)
__device__ __align__(256) float g_s[N_NODES_MAX];        // s[j] = sum_{e: col==j} val[e]
__device__ __align__(256) float g_t[H1];                 // t = sum_i s[i]*relu(a[i])
__device__ unsigned g_ticket;                            // last-block ticket

// ---------------------------------------------------------------------------
// y = x @ W1   (N x 256) @ (256 x 16)
// R4 skeleton (256 thr, 1 row/thread, coalesced LDG -> transposed pad-257
// tile, conflict-free both phases) + packed fma.rn.f32x2 + 64-bit W loads:
// per-kk issue count 21 -> 12.
// ---------------------------------------------------------------------------
__global__ void gemm1_kernel(const float* __restrict__ x,
                             const float* __restrict__ W1, int n) {
    extern __shared__ float smem[];
    float* sW = smem;                    // [D_IN*H1] = 4096 floats (16 KB)
    float* sx = smem + D_IN * H1;        // [KT][257] transposed x tile

    int tid = threadIdx.x;
    for (int i = tid; i < D_IN * H1 / 4; i += G_THREADS)
        reinterpret_cast<float4*>(sW)[i] = reinterpret_cast<const float4*>(W1)[i];

    int row0 = blockIdx.x * G_THREADS;
    int row = row0 + tid;

    unsigned long long acc[8];   // f32x2 pairs: features (0,1)..(14,15)
#pragma unroll
    for (int j = 0; j < 8; j++) acc[j] = 0ull;

    for (int kt = 0; kt < D_IN; kt += KT) {
        __syncthreads();   // protect sx (prev-iter reads / W1 load on iter 0)
        // Stage tile: 256 rows x 32 floats = 2048 float4; 8 per thread.
        // lanes 0..7 cover one row's 8 float4 -> LDG fully coalesced.
#pragma unroll
        for (int i = 0; i < 8; i++) {
            int idx = tid + i * G_THREADS;
            int r = idx >> 3, kv = idx & 7;
            if (row0 + r < n) {
                float4 v = __ldg(reinterpret_cast<const float4*>(
                    x + (size_t)(row0 + r) * D_IN + kt + kv * 4));
                int k = kv * 4;
                sx[(k + 0) * 257 + r] = v.x;   // bank (k+r)%32: conflict-free
                sx[(k + 1) * 257 + r] = v.y;
                sx[(k + 2) * 257 + r] = v.z;
                sx[(k + 3) * 257 + r] = v.w;
            }
        }
        __syncthreads();
#pragma unroll
        for (int kk = 0; kk < KT; kk++) {
            float xs = sx[kk * 257 + tid];
            unsigned long long x2;
            asm("mov.b64 %0, {%1, %1};" : "=l"(x2) : "f"(xs));
            const ulonglong2* wp =
                reinterpret_cast<const ulonglong2*>(sW + (kt + kk) * H1);
            ulonglong2 w01 = wp[0], w23 = wp[1], w45 = wp[2], w67 = wp[3];
            FMA2(acc[0], x2, w01.x); FMA2(acc[1], x2, w01.y);
            FMA2(acc[2], x2, w23.x); FMA2(acc[3], x2, w23.y);
            FMA2(acc[4], x2, w45.x); FMA2(acc[5], x2, w45.y);
            FMA2(acc[6], x2, w67.x); FMA2(acc[7], x2, w67.y);
        }
    }
    if (row < n) {
        ulonglong2* yr = reinterpret_cast<ulonglong2*>(g_y + (size_t)row * H1);
        yr[0] = make_ulonglong2(acc[0], acc[1]);
        yr[1] = make_ulonglong2(acc[2], acc[3]);
        yr[2] = make_ulonglong2(acc[4], acc[5]);
        yr[3] = make_ulonglong2(acc[6], acc[7]);
    }
}

// ---------------------------------------------------------------------------
// Edge pass: a[r] += v * y[c] via red.global.add.v4.f32 (4 lanes per edge)
//            s[c] += v (lane 0 of each quad)
// ---------------------------------------------------------------------------
__global__ void edge_kernel(const int* __restrict__ rows,
                            const int* __restrict__ cols,
                            const float* __restrict__ vals, int e_count) {
    int gid = blockIdx.x * blockDim.x + threadIdx.x;
    int q = gid & 3;           // quarter of the 16-wide feature row
    int e = gid >> 2;
    if (e >= e_count) return;

    int r = __ldg(rows + e);
    int c = __ldg(cols + e);
    float v = __ldg(vals + e);

    const float4 yv = __ldg(reinterpret_cast<const float4*>(g_y + (size_t)c * H1 + q * 4));
    float px = v * yv.x, py = v * yv.y, pz = v * yv.z, pw = v * yv.w;
    float* dst = g_a + (size_t)r * H1 + q * 4;
    asm volatile("red.global.add.v4.f32 [%0], {%1, %2, %3, %4};"
                 :: "l"(dst), "f"(px), "f"(py), "f"(pz), "f"(pw) : "memory");
    if (q == 0) atomicAdd(&g_s[c], v);
}

// ---------------------------------------------------------------------------
// t[f] = sum_i s[i] * relu(a[i][f]); self-cleans g_a/g_s; last block computes
// the final output and cleans g_t/g_ticket.
// ---------------------------------------------------------------------------
__global__ void reduce_final_kernel(int n,
                                    const float* __restrict__ W2,
                                    const float* __restrict__ w_out,
                                    const float* __restrict__ b_out,
                                    float* __restrict__ out) {
    __shared__ float4 red[256];
    __shared__ bool is_last;
    int tid = threadIdx.x;
    int g = tid & 3;  // feature group: covers features [4g, 4g+4)
    const float4 z4 = {0.f, 0.f, 0.f, 0.f};
    float4 acc = z4;
    int total = n * 4;
    int stride = gridDim.x * blockDim.x;
    for (int idx = blockIdx.x * blockDim.x + tid; idx < total; idx += stride) {
        int i = idx >> 2;
        float4* ap = reinterpret_cast<float4*>(g_a + (size_t)i * H1 + g * 4);
        float4 av = *ap;
        float s = 0.0f;
        if (g == 0) { s = g_s[i]; g_s[i] = 0.0f; }   // sole reader of g_s[i]
        s = __shfl_sync(0xffffffffu, s, (tid & 31) & ~3);
        *ap = z4;                                     // self-clean g_a
        acc.x += s * fmaxf(av.x, 0.f);
        acc.y += s * fmaxf(av.y, 0.f);
        acc.z += s * fmaxf(av.z, 0.f);
        acc.w += s * fmaxf(av.w, 0.f);
    }
    red[tid] = acc;
    __syncthreads();
#pragma unroll
    for (int off = 128; off >= 4; off >>= 1) {
        if (tid < off) {
            float4 o = red[tid + off];
            red[tid].x += o.x; red[tid].y += o.y; red[tid].z += o.z; red[tid].w += o.w;
        }
        __syncthreads();
    }
    if (tid < 4) {
        float4 r4 = red[tid];
        float* dst = g_t + tid * 4;
        asm volatile("red.global.add.v4.f32 [%0], {%1, %2, %3, %4};"
                     :: "l"(dst), "f"(r4.x), "f"(r4.y), "f"(r4.z), "f"(r4.w) : "memory");
    }
    __threadfence();
    if (tid == 0) {
        unsigned done = atomicAdd(&g_ticket, 1u);
        is_last = (done == gridDim.x - 1);
    }
    __syncthreads();
    if (is_last) {
        __threadfence();  // pair with producers' fences
        float z = 0.0f;
        if (tid < H2) {
#pragma unroll
            for (int fi = 0; fi < H1; fi++) z += g_t[fi] * W2[fi * H2 + tid];
        }
        __syncthreads();
        if (tid < H1) g_t[tid] = 0.0f;   // self-clean g_t
        if (tid == 0) g_ticket = 0u;     // self-clean ticket
        if (tid < H2) {
            float p = z * w_out[tid];
#pragma unroll
            for (int o = 16; o > 0; o >>= 1) p += __shfl_xor_sync(0xffffffffu, p, o);
            if (tid == 0) out[0] = 1.0f / (1.0f + expf(-(p + b_out[0])));
        }
    }
}

// ---------------------------------------------------------------------------
extern "C" void kernel_launch(void* const* d_in, const int* in_sizes, int n_in,
                              void* d_out, int out_size) {
    const float* x     = (const float*)d_in[0];
    const float* vals  = (const float*)d_in[1];
    const float* W1    = (const float*)d_in[2];
    const float* W2    = (const float*)d_in[3];
    const float* w_out = (const float*)d_in[4];
    const float* b_out = (const float*)d_in[5];
    const int*   rows  = (const int*)d_in[6];
    const int*   cols  = (const int*)d_in[7];

    int n = in_sizes[0] / D_IN;   // 100000
    int e = in_sizes[1];          // 3200000

    int smem_bytes = (D_IN * H1 + KT * 257) * sizeof(float);  // 49280 B
    cudaFuncSetAttribute(gemm1_kernel,
                         cudaFuncAttributeMaxDynamicSharedMemorySize, smem_bytes);

    gemm1_kernel<<<(n + G_THREADS - 1) / G_THREADS, G_THREADS, smem_bytes>>>(x, W1, n);
    {
        long long work = (long long)e * 4;
        int blocks = (int)((work + 255) / 256);
        edge_kernel<<<blocks, 256>>>(rows, cols, vals, e);
    }
    reduce_final_kernel<<<1024, 256>>>(n, W2, w_out, b_out, (float*)d_out);
}